// round 1
// baseline (speedup 1.0000x reference)
#include <cuda_runtime.h>

// Two-simplicial attention, B=2, S=2048, H=4, D=64, W1=W2=64 (A=C=65).
// One CTA per (b,s,h). fp32 with packed f32x2 FMA.

constexpr int Bc = 2, Sc = 2048, Hc = 4, Dc = 64;
constexpr int AW = 65;               // window size + 1
constexpr float SCALE_F = 0.125f;    // 1/sqrt(64)

// ---- smem layout (floats) ----
// sK1 : 65*64 = 4160
// sK2 : 68*64 = 4352   (rows 65..67 zero)   -- becomes q*k2 in place
// sV1 : 65*64 = 4160
// sV2 : 68*64 = 4352   (rows 65..67 zero)
// sW  : 65*68 = 4420   (zero-initialized; only valid entries written)
// sQ  : 64
// sNP : 13*64 = 832    (per-a-group partial numerators)
// sWR : 8              (per-warp denominator partials)
constexpr int OFF_K1 = 0;
constexpr int OFF_K2 = OFF_K1 + 65 * 64;
constexpr int OFF_V1 = OFF_K2 + 68 * 64;
constexpr int OFF_V2 = OFF_V1 + 65 * 64;
constexpr int OFF_W  = OFF_V2 + 68 * 64;
constexpr int OFF_Q  = OFF_W + 65 * 68;
constexpr int OFF_NP = OFF_Q + 64;
constexpr int OFF_WR = OFF_NP + 13 * 64;
constexpr int SMEM_FLOATS = OFF_WR + 8;
constexpr int SMEM_BYTES = SMEM_FLOATS * 4;   // 89,428 B

__device__ __forceinline__ void ffma2(unsigned long long& acc,
                                      unsigned long long a,
                                      unsigned long long b) {
    asm("fma.rn.f32x2 %0, %1, %2, %0;" : "+l"(acc) : "l"(a), "l"(b));
}
__device__ __forceinline__ unsigned long long dup2(float x) {
    unsigned long long r;
    asm("mov.b64 %0, {%1, %1};" : "=l"(r) : "f"(x));
    return r;
}
__device__ __forceinline__ float2 unpack2(unsigned long long v) {
    float2 f;
    asm("mov.b64 {%0, %1}, %2;" : "=f"(f.x), "=f"(f.y) : "l"(v));
    return f;
}

__global__ void __launch_bounds__(256, 1)
tsa_kernel(const float* __restrict__ q,
           const float* __restrict__ k1,
           const float* __restrict__ k2,
           const float* __restrict__ v1,
           const float* __restrict__ v2,
           float* __restrict__ out) {
    extern __shared__ float sm[];
    float* sK1 = sm + OFF_K1;
    float* sK2 = sm + OFF_K2;
    float* sV1 = sm + OFF_V1;
    float* sV2 = sm + OFF_V2;
    float* sW  = sm + OFF_W;
    float* sQ  = sm + OFF_Q;
    float* sNP = sm + OFF_NP;
    float* sWR = sm + OFF_WR;

    const int tid = threadIdx.x;
    const int bid = blockIdx.x;
    const int h = bid & (Hc - 1);
    const int s = (bid >> 2) & (Sc - 1);
    const int b = bid >> 13;   // / (Hc*Sc)

    // ---- zero pads + sW ----
    if (tid < 192) {               // rows 65..67 of sK2, sV2
        sK2[65 * 64 + tid] = 0.0f;
        sV2[65 * 64 + tid] = 0.0f;
    }
    for (int i = tid; i < 65 * 68; i += 256) sW[i] = 0.0f;

    const int base_sh = ((b * Sc + s) * Hc + h) * Dc;

    // ---- load q and windows ----
    if (tid < 16)
        *(float4*)&sQ[tid * 4] = *(const float4*)&q[base_sh + tid * 4];

    for (int i = tid; i < 65 * 16; i += 256) {
        int r = i >> 4, qd = i & 15;
        int g = s - 64 + r;
        if (g < 0) g = 0;
        int off = ((b * Sc + g) * Hc + h) * Dc + qd * 4;
        int so = r * 64 + qd * 4;
        *(float4*)&sK1[so] = *(const float4*)&k1[off];
        *(float4*)&sK2[so] = *(const float4*)&k2[off];
        *(float4*)&sV1[so] = *(const float4*)&v1[off];
        *(float4*)&sV2[so] = *(const float4*)&v2[off];
    }
    __syncthreads();

    // ---- fold q into k2 in place: qk2[c,d] = q[d]*k2[c,d] ----
    for (int i = tid; i < 65 * 16; i += 256) {
        int r = i >> 4, qd = i & 15;
        float4 v = *(float4*)&sK2[r * 64 + qd * 4];
        float4 qv = *(float4*)&sQ[qd * 4];
        v.x *= qv.x; v.y *= qv.y; v.z *= qv.z; v.w *= qv.w;
        *(float4*)&sK2[r * 64 + qd * 4] = v;
    }
    __syncthreads();

    // ---- phase 3: scores = k1w @ qk2^T, w = exp, masked ----
    // 13 a-groups of 5 x 17 c-groups of 4 = 221 tiles, one per thread.
    const int amin = 64 - s;   // a (or c) valid iff index >= amin
    float dloc = 0.0f;
    if (tid < 221) {
        const int a0 = (tid / 17) * 5;
        const int c0 = (tid % 17) * 4;
        unsigned long long acc[5][4];
#pragma unroll
        for (int i = 0; i < 5; i++)
#pragma unroll
            for (int j = 0; j < 4; j++) acc[i][j] = 0ull;

#pragma unroll
        for (int d = 0; d < 64; d += 4) {
            ulonglong2 ka[5], qc[4];
#pragma unroll
            for (int i = 0; i < 5; i++)
                ka[i] = *reinterpret_cast<const ulonglong2*>(&sK1[(a0 + i) * 64 + d]);
#pragma unroll
            for (int j = 0; j < 4; j++)
                qc[j] = *reinterpret_cast<const ulonglong2*>(&sK2[(c0 + j) * 64 + d]);
#pragma unroll
            for (int i = 0; i < 5; i++)
#pragma unroll
                for (int j = 0; j < 4; j++) {
                    ffma2(acc[i][j], ka[i].x, qc[j].x);
                    ffma2(acc[i][j], ka[i].y, qc[j].y);
                }
        }
#pragma unroll
        for (int i = 0; i < 5; i++)
#pragma unroll
            for (int j = 0; j < 4; j++) {
                int a = a0 + i, c = c0 + j;
                float2 p = unpack2(acc[i][j]);
                float sc = (p.x + p.y) * SCALE_F;
                if (c < 65 && a >= amin && c >= amin) {
                    float wv = __expf(sc);
                    sW[a * 68 + c] = wv;
                    dloc += wv;
                }
            }
    }
    // deterministic denominator: warp reduce -> per-warp slot
#pragma unroll
    for (int o = 16; o; o >>= 1) dloc += __shfl_xor_sync(0xFFFFFFFFu, dloc, o);
    if ((tid & 31) == 0) sWR[tid >> 5] = dloc;
    __syncthreads();

    // ---- phase 4: num[d] = sum_a v1[a,d] * (sum_c w[a,c] v2[c,d]) ----
    // 13 a-groups of 5 x 16 d-quads = 208 tasks, one per thread.
    if (tid < 208) {
        const int qd = tid & 15;
        const int ag = tid >> 4;
        const int a0 = ag * 5;
        unsigned long long tmp[5][2];
#pragma unroll
        for (int i = 0; i < 5; i++) { tmp[i][0] = 0ull; tmp[i][1] = 0ull; }

        for (int c = 0; c < 68; c += 4) {
            ulonglong2 v2d[4];
#pragma unroll
            for (int j = 0; j < 4; j++)
                v2d[j] = *reinterpret_cast<const ulonglong2*>(&sV2[(c + j) * 64 + qd * 4]);
#pragma unroll
            for (int i = 0; i < 5; i++) {
                float4 wr = *(float4*)&sW[(a0 + i) * 68 + c];
                unsigned long long w0 = dup2(wr.x), w1 = dup2(wr.y),
                                   w2 = dup2(wr.z), w3 = dup2(wr.w);
                ffma2(tmp[i][0], w0, v2d[0].x); ffma2(tmp[i][1], w0, v2d[0].y);
                ffma2(tmp[i][0], w1, v2d[1].x); ffma2(tmp[i][1], w1, v2d[1].y);
                ffma2(tmp[i][0], w2, v2d[2].x); ffma2(tmp[i][1], w2, v2d[2].y);
                ffma2(tmp[i][0], w3, v2d[3].x); ffma2(tmp[i][1], w3, v2d[3].y);
            }
        }
        float4 accq = make_float4(0.f, 0.f, 0.f, 0.f);
#pragma unroll
        for (int i = 0; i < 5; i++) {
            float4 v1q = *(float4*)&sV1[(a0 + i) * 64 + qd * 4];
            float2 t0 = unpack2(tmp[i][0]);
            float2 t1 = unpack2(tmp[i][1]);
            accq.x = fmaf(t0.x, v1q.x, accq.x);
            accq.y = fmaf(t0.y, v1q.y, accq.y);
            accq.z = fmaf(t1.x, v1q.z, accq.z);
            accq.w = fmaf(t1.y, v1q.w, accq.w);
        }
        *(float4*)&sNP[ag * 64 + qd * 4] = accq;
    }
    __syncthreads();

    // ---- epilogue: deterministic reduce + divide ----
    if (tid < 64) {
        float den = 1e-8f;
#pragma unroll
        for (int w = 0; w < 8; w++) den += sWR[w];
        float nsum = 0.0f;
#pragma unroll
        for (int g = 0; g < 13; g++) nsum += sNP[g * 64 + tid];
        out[base_sh + tid] = nsum / den;
    }
}

extern "C" void kernel_launch(void* const* d_in, const int* in_sizes, int n_in,
                              void* d_out, int out_size) {
    const float* q  = (const float*)d_in[0];
    const float* k1 = (const float*)d_in[1];
    const float* k2 = (const float*)d_in[2];
    const float* v1 = (const float*)d_in[3];
    const float* v2 = (const float*)d_in[4];
    float* out = (float*)d_out;

    cudaFuncSetAttribute(tsa_kernel, cudaFuncAttributeMaxDynamicSharedMemorySize,
                         SMEM_BYTES);
    dim3 grid(Bc * Sc * Hc);
    tsa_kernel<<<grid, 256, SMEM_BYTES>>>(q, k1, k2, v1, v2, out);
}

// round 2
// speedup vs baseline: 2.1669x; 2.1669x over previous
#include <cuda_runtime.h>

// Two-simplicial attention, B=2, S=2048, H=4, D=64, W1=W2=64 (A=C=65).
// 2 positions per CTA, 512 threads, warp-cooperative f32x2 GEMM phases.

constexpr int Bc = 2, Sc = 2048, Hc = 4, Dc = 64;
constexpr float SCALE_F = 0.125f;
constexpr int P = 2;
constexpr int NT = 512;

// ---- smem layout (floats) ----
constexpr int OFF_K1Q = 0;                       // [P][66][64]  q-folded k1
constexpr int OFF_K2T = OFF_K1Q + P * 66 * 64;   // [64][68]     k2 transposed (cols=window row)
constexpr int OFF_V1  = OFF_K2T + 64 * 68;       // [66][64]
constexpr int OFF_V2  = OFF_K2T + 64 * 68 + 66 * 64;  // [66][64]
constexpr int OFF_W   = OFF_V2 + 66 * 64;        // [P][72][68]
constexpr int OFF_NP  = OFF_W + P * 72 * 68;     // [P][8][64]
constexpr int OFF_DEN = OFF_NP + P * 8 * 64;     // [P][8]
constexpr int SMEM_FLOATS = OFF_DEN + P * 8;
constexpr int SMEM_BYTES = SMEM_FLOATS * 4;      // ~128.3 KB

typedef unsigned long long ull;

__device__ __forceinline__ void ffma2(ull& acc, ull a, ull b) {
    asm("fma.rn.f32x2 %0, %1, %2, %0;" : "+l"(acc) : "l"(a), "l"(b));
}
__device__ __forceinline__ ull pack2(float lo, float hi) {
    ull r;
    asm("mov.b64 %0, {%1, %2};" : "=l"(r) : "f"(lo), "f"(hi));
    return r;
}
__device__ __forceinline__ float2 unpack2(ull v) {
    float2 f;
    asm("mov.b64 {%0, %1}, %2;" : "=f"(f.x), "=f"(f.y) : "l"(v));
    return f;
}

__global__ void __launch_bounds__(NT, 1)
tsa_kernel(const float* __restrict__ q,
           const float* __restrict__ k1,
           const float* __restrict__ k2,
           const float* __restrict__ v1,
           const float* __restrict__ v2,
           float* __restrict__ out) {
    extern __shared__ float sm[];
    const int tid = threadIdx.x;
    const int bid = blockIdx.x;
    const int h  = bid & 3;
    const int st = (bid >> 2) & 1023;
    const int b  = bid >> 12;
    const int s0 = st * 2;

    // ================= stage A: loads =================
    // window rows r=0..65 -> global g = clamp(s0-64+r, 0)
    for (int i = tid; i < 66 * 16; i += NT) {
        int r = i >> 4, dq = i & 15;
        int g = s0 - 64 + r; if (g < 0) g = 0;
        int off = ((b * Sc + g) * Hc + h) * Dc + dq * 4;
        float4 av = *(const float4*)&v1[off];
        *(float4*)&sm[OFF_V1 + r * 64 + dq * 4] = av;
        float4 bv = *(const float4*)&v2[off];
        *(float4*)&sm[OFF_V2 + r * 64 + dq * 4] = bv;
        float4 cv = *(const float4*)&k2[off];
        int d0 = dq * 4;
        sm[OFF_K2T + (d0 + 0) * 68 + r] = cv.x;
        sm[OFF_K2T + (d0 + 1) * 68 + r] = cv.y;
        sm[OFF_K2T + (d0 + 2) * 68 + r] = cv.z;
        sm[OFF_K2T + (d0 + 3) * 68 + r] = cv.w;
    }
    // zero-pad K2T cols 66,67
    for (int i = tid; i < 128; i += NT) {
        int d = i >> 1, cc = 66 + (i & 1);
        sm[OFF_K2T + d * 68 + cc] = 0.0f;
    }
    // q-folded k1 per position
    for (int i = tid; i < P * 66 * 16; i += NT) {
        int p = i / (66 * 16);
        int rr = i - p * 66 * 16;
        int r = rr >> 4, dq = rr & 15;
        int g = s0 - 64 + r; if (g < 0) g = 0;
        int off  = ((b * Sc + g) * Hc + h) * Dc + dq * 4;
        int qoff = ((b * Sc + s0 + p) * Hc + h) * Dc + dq * 4;
        float4 kv = *(const float4*)&k1[off];
        float4 qv = *(const float4*)&q[qoff];
        kv.x *= qv.x; kv.y *= qv.y; kv.z *= qv.z; kv.w *= qv.w;
        *(float4*)&sm[OFF_K1Q + (p * 66 + r) * 64 + dq * 4] = kv;
    }
    __syncthreads();

    // ================= phase 3: scores + exp =================
    const int wid = tid >> 5, lane = tid & 31;
    const int p  = wid >> 3;          // position 0/1
    const int wa = wid & 7;           // a-block
    const int a0 = wa * 9;
    const int sp = s0 + p;
    const int amin = 64 - sp;         // a (or c) valid iff >= amin
    const float* k1q = &sm[OFF_K1Q + p * 66 * 64];
    float* sW = &sm[OFF_W + p * 72 * 68];

    int rowi[9];
#pragma unroll
    for (int i = 0; i < 9; i++) {
        int r = p + a0 + i;
        rowi[i] = (r > 65) ? 65 : r;
    }

    ull acc[9][2];
#pragma unroll
    for (int i = 0; i < 9; i++) { acc[i][0] = 0ull; acc[i][1] = 0ull; }

    const float* k2c0 = &sm[OFF_K2T + p + lane];
    const float* k2c1 = &sm[OFF_K2T + p + lane + 32];

#pragma unroll 4
    for (int d = 0; d < 64; d += 4) {
        float c00 = k2c0[(d    ) * 68], c01 = k2c1[(d    ) * 68];
        float c10 = k2c0[(d + 1) * 68], c11 = k2c1[(d + 1) * 68];
        float c20 = k2c0[(d + 2) * 68], c21 = k2c1[(d + 2) * 68];
        float c30 = k2c0[(d + 3) * 68], c31 = k2c1[(d + 3) * 68];
        ull kc0a = pack2(c00, c10), kc1a = pack2(c01, c11);
        ull kc0b = pack2(c20, c30), kc1b = pack2(c21, c31);
#pragma unroll
        for (int i = 0; i < 9; i++) {
            ulonglong2 a4 = *(const ulonglong2*)&k1q[rowi[i] * 64 + d];
            ffma2(acc[i][0], a4.x, kc0a);
            ffma2(acc[i][1], a4.x, kc1a);
            ffma2(acc[i][0], a4.y, kc0b);
            ffma2(acc[i][1], a4.y, kc1b);
        }
    }

    float dloc = 0.0f;
#pragma unroll
    for (int i = 0; i < 9; i++) {
        int a = a0 + i;
        bool av = (a < 65) && (a >= amin);
#pragma unroll
        for (int jc = 0; jc < 2; jc++) {
            int c = lane + 32 * jc;
            float2 t = unpack2(acc[i][jc]);
            float sc = (t.x + t.y) * SCALE_F;
            float wv = 0.0f;
            if (av && c >= amin) { wv = __expf(sc); dloc += wv; }
            sW[a * 68 + c] = wv;   // zeros for invalid -> phase 4 unguarded
        }
    }
    // tail column c = 64 (always window-valid)
    {
        float x0 = sm[OFF_K2T + lane * 68 + p + 64];
        float x1 = sm[OFF_K2T + (lane + 32) * 68 + p + 64];
#pragma unroll
        for (int i = 0; i < 9; i++) {
            float t = k1q[rowi[i] * 64 + lane] * x0
                    + k1q[rowi[i] * 64 + lane + 32] * x1;
#pragma unroll
            for (int o = 16; o; o >>= 1) t += __shfl_xor_sync(0xFFFFFFFFu, t, o);
            if (lane == 0) {
                int a = a0 + i;
                float wv = 0.0f;
                if (a < 65 && a >= amin) { wv = __expf(t * SCALE_F); dloc += wv; }
                sW[a * 68 + 64] = wv;
            }
        }
    }
#pragma unroll
    for (int o = 16; o; o >>= 1) dloc += __shfl_xor_sync(0xFFFFFFFFu, dloc, o);
    if (lane == 0) sm[OFF_DEN + p * 8 + wa] = dloc;
    __syncthreads();

    // ================= phase 4: num = sum_a v1[a] * (W[a,:] @ V2) =================
    ull tmp[9][2];
#pragma unroll
    for (int i = 0; i < 9; i++) { tmp[i][0] = 0ull; tmp[i][1] = 0ull; }

    const float* v2b = &sm[OFF_V2 + p * 64];   // row p+c at offset c*64

#pragma unroll 4
    for (int c = 0; c < 64; c += 2) {
        float va0 = v2b[(c    ) * 64 + lane];
        float vb0 = v2b[(c    ) * 64 + lane + 32];
        float va1 = v2b[(c + 1) * 64 + lane];
        float vb1 = v2b[(c + 1) * 64 + lane + 32];
        ull vp0 = pack2(va0, va1);   // d = lane     : (c, c+1)
        ull vp1 = pack2(vb0, vb1);   // d = lane+32  : (c, c+1)
#pragma unroll
        for (int i = 0; i < 9; i++) {
            ull wp = *(const ull*)&sW[(a0 + i) * 68 + c];  // broadcast LDS.64
            ffma2(tmp[i][0], wp, vp0);
            ffma2(tmp[i][1], wp, vp1);
        }
    }
    // tail c = 64 + v1 contraction
    float v64a = v2b[64 * 64 + lane];
    float v64b = v2b[64 * 64 + lane + 32];
    float nsum0 = 0.0f, nsum1 = 0.0f;
#pragma unroll
    for (int i = 0; i < 9; i++) {
        float w64 = sW[(a0 + i) * 68 + 64];
        float2 t0 = unpack2(tmp[i][0]);
        float2 t1 = unpack2(tmp[i][1]);
        float ta = t0.x + t0.y + w64 * v64a;
        float tb = t1.x + t1.y + w64 * v64b;
        int r = rowi[i];  // invalid a -> tmp==0, product 0 regardless of v1
        ta *= sm[OFF_V1 + r * 64 + lane];
        tb *= sm[OFF_V1 + r * 64 + lane + 32];
        nsum0 += ta;
        nsum1 += tb;
    }
    sm[OFF_NP + (p * 8 + wa) * 64 + lane]      = nsum0;
    sm[OFF_NP + (p * 8 + wa) * 64 + lane + 32] = nsum1;
    __syncthreads();

    // ================= epilogue =================
    if (tid < P * 64) {
        int pp = tid >> 6, d = tid & 63;
        float den = 1e-8f;
#pragma unroll
        for (int w = 0; w < 8; w++) den += sm[OFF_DEN + pp * 8 + w];
        float num = 0.0f;
#pragma unroll
        for (int w = 0; w < 8; w++) num += sm[OFF_NP + (pp * 8 + w) * 64 + d];
        int o = ((b * Sc + s0 + pp) * Hc + h) * Dc + d;
        out[o] = num / den;
    }
}

extern "C" void kernel_launch(void* const* d_in, const int* in_sizes, int n_in,
                              void* d_out, int out_size) {
    const float* q  = (const float*)d_in[0];
    const float* k1 = (const float*)d_in[1];
    const float* k2 = (const float*)d_in[2];
    const float* v1 = (const float*)d_in[3];
    const float* v2 = (const float*)d_in[4];
    float* out = (float*)d_out;

    cudaFuncSetAttribute(tsa_kernel, cudaFuncAttributeMaxDynamicSharedMemorySize,
                         SMEM_BYTES);
    dim3 grid(Bc * (Sc / P) * Hc);
    tsa_kernel<<<grid, NT, SMEM_BYTES>>>(q, k1, k2, v1, v2, out);
}